// round 7
// baseline (speedup 1.0000x reference)
#include <cuda_runtime.h>
#include <string.h>

#define D128 128
#define H0 64
#define W0 96
#define HW0 (H0 * W0)   // 6144

// fp32 pyramids (HWD layout). L0 786432, L1 196608, L2 49152, L3 12288.
__device__ __align__(16) float g_f1[1044480];
__device__ __align__(16) float g_f2[1044480];

typedef unsigned long long ull;

__device__ __forceinline__ void fma2(ull& d, ull a, ull b) {
    asm("fma.rn.f32x2 %0, %1, %2, %3;" : "=l"(d) : "l"(a), "l"(b), "l"(d));
}
__device__ __forceinline__ ulonglong2 asu2(float4 v) {
    ulonglong2 r; memcpy(&r, &v, 16); return r;
}

// ---------------------------------------------------------------------------
// Kernel 1: fused transpose + full pyramid build. One block per 8x8 pixel
// tile per map, 512 threads (4 LDG.128/thread). grid (96,1,2).
// ---------------------------------------------------------------------------
__global__ __launch_bounds__(512) void build_kernel(const float* __restrict__ f1,
                                                    const float* __restrict__ f2) {
    __shared__ float s0[8][8][128];   // 32KB
    __shared__ float s1[4][4][128];   // 8KB
    __shared__ float s2[2][2][128];   // 2KB
    int map = blockIdx.z;
    const float* in = map ? f2 : f1;
    float* base = map ? g_f2 : g_f1;
    int tx0 = (blockIdx.x % 12) * 8;
    int ty0 = (blockIdx.x / 12) * 8;
    int t = threadIdx.x;

    // load: channel d = t>>2; selector s = t&3 -> rows {2s, 2s+1}, both halves
    {
        int d = t >> 2;
        int sl = t & 3;
        const float* src = in + d * HW0 + ty0 * W0 + tx0;
        float4 v00 = *(const float4*)(src + (2 * sl) * W0);
        float4 v01 = *(const float4*)(src + (2 * sl) * W0 + 4);
        float4 v10 = *(const float4*)(src + (2 * sl + 1) * W0);
        float4 v11 = *(const float4*)(src + (2 * sl + 1) * W0 + 4);
        int y0 = 2 * sl, y1 = 2 * sl + 1;
        s0[y0][0][d] = v00.x; s0[y0][1][d] = v00.y; s0[y0][2][d] = v00.z; s0[y0][3][d] = v00.w;
        s0[y0][4][d] = v01.x; s0[y0][5][d] = v01.y; s0[y0][6][d] = v01.z; s0[y0][7][d] = v01.w;
        s0[y1][0][d] = v10.x; s0[y1][1][d] = v10.y; s0[y1][2][d] = v10.z; s0[y1][3][d] = v10.w;
        s0[y1][4][d] = v11.x; s0[y1][5][d] = v11.y; s0[y1][6][d] = v11.z; s0[y1][7][d] = v11.w;
    }
    __syncthreads();

    // write transposed L0: 2048 float4, 4 per thread
#pragma unroll
    for (int i = 0; i < 4; i++) {
        int idx = i * 512 + t;
        int c4 = idx & 31;
        int px = idx >> 5;          // 0..63
        int y = px >> 3, x = px & 7;
        float4 w = *(float4*)&s0[y][x][c4 * 4];
        int gp = (ty0 + y) * W0 + tx0 + x;
        *(float4*)(base + gp * D128 + c4 * 4) = w;
    }

    // L1: 16 px x 128 ch = 2048 elems, 4 per thread
#pragma unroll
    for (int i = 0; i < 4; i++) {
        int idx = i * 512 + t;
        int c = idx & 127;
        int px = idx >> 7;          // 0..15
        int y = px >> 2, x = px & 3;
        float r = 0.25f * (s0[2*y][2*x][c] + s0[2*y][2*x+1][c]
                         + s0[2*y+1][2*x][c] + s0[2*y+1][2*x+1][c]);
        s1[y][x][c] = r;
        int gp = (ty0 / 2 + y) * 48 + tx0 / 2 + x;
        base[786432 + gp * D128 + c] = r;
    }
    __syncthreads();

    // L2: 4 px x 128 ch = 512 elems, 1 per thread
    {
        int c = t & 127;
        int px = t >> 7;            // 0..3
        int y = px >> 1, x = px & 1;
        float r = 0.25f * (s1[2*y][2*x][c] + s1[2*y][2*x+1][c]
                         + s1[2*y+1][2*x][c] + s1[2*y+1][2*x+1][c]);
        s2[y][x][c] = r;
        int gp = (ty0 / 4 + y) * 24 + tx0 / 4 + x;
        base[983040 + gp * D128 + c] = r;
    }
    __syncthreads();

    // L3: 1 px x 128 ch
    if (t < 128) {
        float r = 0.25f * (s2[0][0][t] + s2[0][1][t] + s2[1][0][t] + s2[1][1][t]);
        int gp = (ty0 / 8) * 12 + tx0 / 8;
        base[1032192 + gp * D128 + t] = r;
    }
}

// ---------------------------------------------------------------------------
// Kernel 2: fused correlation lookup. 256 threads per pixel PAIR.
// Dot phase: 2 positions per 8-lane group per pass (8 batched LDG.128 per
// thread -> MLP 8), packed fma.rn.f32x2, 4 passes.
// ---------------------------------------------------------------------------
__global__ __launch_bounds__(256, 4) void corr_kernel(const float* __restrict__ coords,
                                                      float* __restrict__ out) {
    int gq = (blockIdx.x % 148) * 28 + blockIdx.x / 148;
    if (gq >= 4080) return;

    int lvl, q;
    if (gq < 3072)      { lvl = 0; q = gq; }
    else if (gq < 3840) { lvl = 1; q = gq - 3072; }
    else if (gq < 4032) { lvl = 2; q = gq - 3840; }
    else                { lvl = 3; q = gq - 4032; }

    int loff, ooff;
    switch (lvl) {
        case 0:  loff = 0;       ooff = 0;      break;
        case 1:  loff = 786432;  ooff = 497664; break;
        case 2:  loff = 983040;  ooff = 622080; break;
        default: loff = 1032192; ooff = 653184; break;
    }
    const int Hl = H0 >> lvl, Wl = W0 >> lvl;

    int t    = threadIdx.x;
    int side = t >> 7;
    int tt   = t & 127;
    int p    = 2 * q + side;
    int py = p / Wl, px = p - py * Wl;

    __shared__ float sh_c[2][2];
    __shared__ int   sh_addr[2][128];
    __shared__ float sh_dot[2][112];

    int w    = tt >> 5;
    int lane = tt & 31;
    int sub  = lane & 7;
    int quad = lane >> 3;

    // --- coords at this level (jax.image.resize linear antialias semantics)
    if (tt < 2) {
        float c;
        if (lvl == 0) {
            c = coords[tt * HW0 + p];
        } else {
            int   f    = 1 << lvl;
            float invf = 1.0f / (float)f;
            float sy = ((float)py + 0.5f) * (float)f - 0.5f;
            float sx = ((float)px + 0.5f) * (float)f - 0.5f;
            int jylo = max(0,      (int)floorf(sy - (float)f) + 1);
            int jyhi = min(H0 - 1, (int)floorf(sy + (float)f));
            int jxlo = max(0,      (int)floorf(sx - (float)f) + 1);
            int jxhi = min(W0 - 1, (int)floorf(sx + (float)f));
            float wyTot = 0.f, wxTot = 0.f;
            for (int j = jylo; j <= jyhi; j++) wyTot += 1.f - fabsf(sy - (float)j) * invf;
            for (int j = jxlo; j <= jxhi; j++) wxTot += 1.f - fabsf(sx - (float)j) * invf;
            const float* cc = coords + tt * HW0;
            float acc = 0.f;
            for (int jy = jylo; jy <= jyhi; jy++) {
                float wy = 1.f - fabsf(sy - (float)jy) * invf;
                float ra = 0.f;
                for (int jx = jxlo; jx <= jxhi; jx++)
                    ra += (1.f - fabsf(sx - (float)jx) * invf) * cc[jy * W0 + jx];
                acc += wy * ra;
            }
            c = acc / (wyTot * wxTot) * invf;
        }
        sh_c[side][tt] = c;
    }

    // --- f1 fp32 chunks for this lane
    const float4* f1v = (const float4*)(g_f1 + loff + p * D128);
    ulonglong2 a0 = asu2(f1v[sub]);
    ulonglong2 a1 = asu2(f1v[8 + sub]);
    ulonglong2 a2 = asu2(f1v[16 + sub]);
    ulonglong2 a3 = asu2(f1v[24 + sub]);

    __syncthreads();

    float cx = sh_c[side][0], cy = sh_c[side][1];
    int ix = (int)floorf(cx);
    int iy = (int)floorf(cy);

    // --- precompute clamped tap base addresses (float4 units); pad 100..127
    {
        int ty = tt / 10, tx = tt - ty * 10;
        int gy = min(max(iy + ty - 4, 0), Hl - 1);
        int gx = min(max(ix + tx - 4, 0), Wl - 1);
        sh_addr[side][tt] = (tt < 100) ? (gy * Wl + gx) * 32 : 0;
    }
    __syncthreads();

    const float4* f2base = (const float4*)(g_f2 + loff);

    // --- 100 corner dots per side: 4 passes x (16 groups x 2 positions)
#pragma unroll
    for (int j = 0; j < 4; j++) {
        int pos0 = j * 32 + (w * 4 + quad) * 2;   // even, 0..126
        int pos1 = pos0 + 1;
        const float4* qa = f2base + sh_addr[side][pos0];
        const float4* qb = f2base + sh_addr[side][pos1];
        float4 A = qa[sub];
        float4 B = qa[8 + sub];
        float4 C = qa[16 + sub];
        float4 D = qa[24 + sub];
        float4 E = qb[sub];
        float4 F = qb[8 + sub];
        float4 G = qb[16 + sub];
        float4 H = qb[24 + sub];
        ulonglong2 u;
        ull acc0 = 0ULL, acc1 = 0ULL;
        u = asu2(A); fma2(acc0, a0.x, u.x); fma2(acc0, a0.y, u.y);
        u = asu2(B); fma2(acc0, a1.x, u.x); fma2(acc0, a1.y, u.y);
        u = asu2(C); fma2(acc0, a2.x, u.x); fma2(acc0, a2.y, u.y);
        u = asu2(D); fma2(acc0, a3.x, u.x); fma2(acc0, a3.y, u.y);
        u = asu2(E); fma2(acc1, a0.x, u.x); fma2(acc1, a0.y, u.y);
        u = asu2(F); fma2(acc1, a1.x, u.x); fma2(acc1, a1.y, u.y);
        u = asu2(G); fma2(acc1, a2.x, u.x); fma2(acc1, a2.y, u.y);
        u = asu2(H); fma2(acc1, a3.x, u.x); fma2(acc1, a3.y, u.y);
        float2 f0; memcpy(&f0, &acc0, 8);
        float2 f1r; memcpy(&f1r, &acc1, 8);
        float s0 = f0.x + f0.y;
        float s1 = f1r.x + f1r.y;
        s0 += __shfl_xor_sync(0xffffffffu, s0, 1);
        s1 += __shfl_xor_sync(0xffffffffu, s1, 1);
        s0 += __shfl_xor_sync(0xffffffffu, s0, 2);
        s1 += __shfl_xor_sync(0xffffffffu, s1, 2);
        s0 += __shfl_xor_sync(0xffffffffu, s0, 4);
        s1 += __shfl_xor_sync(0xffffffffu, s1, 4);
        if (sub == 0) {
            if (pos0 < 100) sh_dot[side][pos0] = s0;
            if (pos1 < 100) sh_dot[side][pos1] = s1;
        }
    }
    __syncthreads();

    // --- bilinear combine: t<162 -> (k = t/2, sd = t&1); pairwise 8B stores
    if (t < 162) {
        int k  = t >> 1;
        int sd = t & 1;
        float cx2 = sh_c[sd][0], cy2 = sh_c[sd][1];
        int ix2 = (int)floorf(cx2);
        int iy2 = (int)floorf(cy2);
        int dxi = k / 9, dyi = k - dxi * 9;
        float xq = fminf(fmaxf(cx2 + (float)(dxi - 4), 0.f), (float)(Wl - 1));
        float yq = fminf(fmaxf(cy2 + (float)(dyi - 4), 0.f), (float)(Hl - 1));
        float x0f = floorf(xq), y0f = floorf(yq);
        float wx1 = xq - x0f,  wy1 = yq - y0f;
        float wx0 = 1.f - wx1, wy0 = 1.f - wy1;
        int t0x = min(max((int)x0f - ix2 + 4, 0), 9), t1x = min(t0x + 1, 9);
        int t0y = min(max((int)y0f - iy2 + 4, 0), 9), t1y = min(t0y + 1, 9);
        float v = wy0 * (wx0 * sh_dot[sd][t0y * 10 + t0x] + wx1 * sh_dot[sd][t0y * 10 + t1x])
                + wy1 * (wx0 * sh_dot[sd][t1y * 10 + t0x] + wx1 * sh_dot[sd][t1y * 10 + t1x]);
        out[ooff + k * (Hl * Wl) + 2 * q + sd] = v * 0.08838834764831845f;  // 1/sqrt(128)
    }
}

// ---------------------------------------------------------------------------
extern "C" void kernel_launch(void* const* d_in, const int* in_sizes, int n_in,
                              void* d_out, int out_size) {
    const float* f1     = (const float*)d_in[0];
    const float* f2     = (const float*)d_in[1];
    const float* coords = (const float*)d_in[2];
    float* out = (float*)d_out;

    build_kernel<<<dim3(96, 1, 2), 512>>>(f1, f2);
    corr_kernel<<<4144, 256>>>(coords, out);
}

// round 8
// speedup vs baseline: 1.0428x; 1.0428x over previous
#include <cuda_runtime.h>
#include <string.h>

#define D128 128
#define H0 64
#define W0 96
#define HW0 (H0 * W0)   // 6144

// fp32 pyramids (HWD layout). L0 786432, L1 196608, L2 49152, L3 12288.
__device__ __align__(16) float g_f1[1044480];
__device__ __align__(16) float g_f2[1044480];

typedef unsigned long long ull;

__device__ __forceinline__ void fma2(ull& d, ull a, ull b) {
    asm("fma.rn.f32x2 %0, %1, %2, %3;" : "=l"(d) : "l"(a), "l"(b), "l"(d));
}
__device__ __forceinline__ ulonglong2 asu2(float4 v) {
    ulonglong2 r; memcpy(&r, &v, 16); return r;
}

// ---------------------------------------------------------------------------
// Kernel 1: fused transpose + full pyramid build. One block per 8x8 pixel
// tile per map, 512 threads (4 LDG.128/thread). grid (96,1,2).
// ---------------------------------------------------------------------------
__global__ __launch_bounds__(512) void build_kernel(const float* __restrict__ f1,
                                                    const float* __restrict__ f2) {
    __shared__ float s0[8][8][128];   // 32KB
    __shared__ float s1[4][4][128];   // 8KB
    __shared__ float s2[2][2][128];   // 2KB
    int map = blockIdx.z;
    const float* in = map ? f2 : f1;
    float* base = map ? g_f2 : g_f1;
    int tx0 = (blockIdx.x % 12) * 8;
    int ty0 = (blockIdx.x / 12) * 8;
    int t = threadIdx.x;

    // load: channel d = t>>2; selector sl = t&3 -> rows {2sl, 2sl+1}
    {
        int d = t >> 2;
        int sl = t & 3;
        const float* src = in + d * HW0 + ty0 * W0 + tx0;
        float4 v00 = *(const float4*)(src + (2 * sl) * W0);
        float4 v01 = *(const float4*)(src + (2 * sl) * W0 + 4);
        float4 v10 = *(const float4*)(src + (2 * sl + 1) * W0);
        float4 v11 = *(const float4*)(src + (2 * sl + 1) * W0 + 4);
        int y0 = 2 * sl, y1 = 2 * sl + 1;
        s0[y0][0][d] = v00.x; s0[y0][1][d] = v00.y; s0[y0][2][d] = v00.z; s0[y0][3][d] = v00.w;
        s0[y0][4][d] = v01.x; s0[y0][5][d] = v01.y; s0[y0][6][d] = v01.z; s0[y0][7][d] = v01.w;
        s0[y1][0][d] = v10.x; s0[y1][1][d] = v10.y; s0[y1][2][d] = v10.z; s0[y1][3][d] = v10.w;
        s0[y1][4][d] = v11.x; s0[y1][5][d] = v11.y; s0[y1][6][d] = v11.z; s0[y1][7][d] = v11.w;
    }
    __syncthreads();

    // write transposed L0: 2048 float4, 4 per thread
#pragma unroll
    for (int i = 0; i < 4; i++) {
        int idx = i * 512 + t;
        int c4 = idx & 31;
        int px = idx >> 5;          // 0..63
        int y = px >> 3, x = px & 7;
        float4 w = *(float4*)&s0[y][x][c4 * 4];
        int gp = (ty0 + y) * W0 + tx0 + x;
        *(float4*)(base + gp * D128 + c4 * 4) = w;
    }

    // L1: 16 px x 128 ch = 2048 elems, 4 per thread
#pragma unroll
    for (int i = 0; i < 4; i++) {
        int idx = i * 512 + t;
        int c = idx & 127;
        int px = idx >> 7;          // 0..15
        int y = px >> 2, x = px & 3;
        float r = 0.25f * (s0[2*y][2*x][c] + s0[2*y][2*x+1][c]
                         + s0[2*y+1][2*x][c] + s0[2*y+1][2*x+1][c]);
        s1[y][x][c] = r;
        int gp = (ty0 / 2 + y) * 48 + tx0 / 2 + x;
        base[786432 + gp * D128 + c] = r;
    }
    __syncthreads();

    // L2: 4 px x 128 ch = 512 elems, 1 per thread
    {
        int c = t & 127;
        int px = t >> 7;            // 0..3
        int y = px >> 1, x = px & 1;
        float r = 0.25f * (s1[2*y][2*x][c] + s1[2*y][2*x+1][c]
                         + s1[2*y+1][2*x][c] + s1[2*y+1][2*x+1][c]);
        s2[y][x][c] = r;
        int gp = (ty0 / 4 + y) * 24 + tx0 / 4 + x;
        base[983040 + gp * D128 + c] = r;
    }
    __syncthreads();

    // L3: 1 px x 128 ch
    if (t < 128) {
        float r = 0.25f * (s2[0][0][t] + s2[0][1][t] + s2[1][0][t] + s2[1][1][t]);
        int gp = (ty0 / 8) * 12 + tx0 / 8;
        base[1032192 + gp * D128 + t] = r;
    }
}

// ---------------------------------------------------------------------------
// Kernel 2: fused correlation lookup. 256 threads per pixel PAIR.
// R6 dot structure (1 position per 8-lane group per pass, 7 passes) with
// q-loads interleaved 2+2 to shrink live registers; forced 7 blocks/SM.
// ---------------------------------------------------------------------------
__global__ __launch_bounds__(256, 7) void corr_kernel(const float* __restrict__ coords,
                                                      float* __restrict__ out) {
    int gq = (blockIdx.x % 148) * 28 + blockIdx.x / 148;
    if (gq >= 4080) return;

    int lvl, q;
    if (gq < 3072)      { lvl = 0; q = gq; }
    else if (gq < 3840) { lvl = 1; q = gq - 3072; }
    else if (gq < 4032) { lvl = 2; q = gq - 3840; }
    else                { lvl = 3; q = gq - 4032; }

    int loff, ooff;
    switch (lvl) {
        case 0:  loff = 0;       ooff = 0;      break;
        case 1:  loff = 786432;  ooff = 497664; break;
        case 2:  loff = 983040;  ooff = 622080; break;
        default: loff = 1032192; ooff = 653184; break;
    }
    const int Hl = H0 >> lvl, Wl = W0 >> lvl;

    int t    = threadIdx.x;
    int side = t >> 7;
    int tt   = t & 127;
    int p    = 2 * q + side;
    int py = p / Wl, px = p - py * Wl;

    __shared__ float sh_c[2][2];
    __shared__ int   sh_addr[2][128];
    __shared__ float sh_dot[2][112];

    int w    = tt >> 5;
    int lane = tt & 31;
    int sub  = lane & 7;
    int quad = lane >> 3;

    // --- coords at this level (jax.image.resize linear antialias semantics)
    if (tt < 2) {
        float c;
        if (lvl == 0) {
            c = coords[tt * HW0 + p];
        } else {
            int   f    = 1 << lvl;
            float invf = 1.0f / (float)f;
            float sy = ((float)py + 0.5f) * (float)f - 0.5f;
            float sx = ((float)px + 0.5f) * (float)f - 0.5f;
            int jylo = max(0,      (int)floorf(sy - (float)f) + 1);
            int jyhi = min(H0 - 1, (int)floorf(sy + (float)f));
            int jxlo = max(0,      (int)floorf(sx - (float)f) + 1);
            int jxhi = min(W0 - 1, (int)floorf(sx + (float)f));
            float wyTot = 0.f, wxTot = 0.f;
            for (int j = jylo; j <= jyhi; j++) wyTot += 1.f - fabsf(sy - (float)j) * invf;
            for (int j = jxlo; j <= jxhi; j++) wxTot += 1.f - fabsf(sx - (float)j) * invf;
            const float* cc = coords + tt * HW0;
            float acc = 0.f;
            for (int jy = jylo; jy <= jyhi; jy++) {
                float wy = 1.f - fabsf(sy - (float)jy) * invf;
                float ra = 0.f;
                for (int jx = jxlo; jx <= jxhi; jx++)
                    ra += (1.f - fabsf(sx - (float)jx) * invf) * cc[jy * W0 + jx];
                acc += wy * ra;
            }
            c = acc / (wyTot * wxTot) * invf;
        }
        sh_c[side][tt] = c;
    }

    // --- f1 fp32 chunks for this lane
    const float4* f1v = (const float4*)(g_f1 + loff + p * D128);
    ulonglong2 a0 = asu2(f1v[sub]);
    ulonglong2 a1 = asu2(f1v[8 + sub]);
    ulonglong2 a2 = asu2(f1v[16 + sub]);
    ulonglong2 a3 = asu2(f1v[24 + sub]);

    __syncthreads();

    float cx = sh_c[side][0], cy = sh_c[side][1];
    int ix = (int)floorf(cx);
    int iy = (int)floorf(cy);

    // --- precompute clamped tap base addresses (float4 units); pad 100..127
    {
        int ty = tt / 10, tx = tt - ty * 10;
        int gy = min(max(iy + ty - 4, 0), Hl - 1);
        int gx = min(max(ix + tx - 4, 0), Wl - 1);
        sh_addr[side][tt] = (tt < 100) ? (gy * Wl + gx) * 32 : 0;
    }
    __syncthreads();

    const float4* f2base = (const float4*)(g_f2 + loff);

    // --- 100 corner dots per side: 7 passes x (4 warps x 4 positions)
#pragma unroll
    for (int j = 0; j < 7; j++) {
        int pos  = j * 16 + w * 4 + quad;     // 0..111
        int posc = min(pos, 99);
        const float4* qv = f2base + sh_addr[side][posc];
        ulonglong2 u;
        ull acc = 0ULL;
        {
            float4 A = qv[sub];
            float4 B = qv[8 + sub];
            u = asu2(A); fma2(acc, a0.x, u.x); fma2(acc, a0.y, u.y);
            u = asu2(B); fma2(acc, a1.x, u.x); fma2(acc, a1.y, u.y);
        }
        {
            float4 C = qv[16 + sub];
            float4 D = qv[24 + sub];
            u = asu2(C); fma2(acc, a2.x, u.x); fma2(acc, a2.y, u.y);
            u = asu2(D); fma2(acc, a3.x, u.x); fma2(acc, a3.y, u.y);
        }
        float2 fr; memcpy(&fr, &acc, 8);
        float s = fr.x + fr.y;
        s += __shfl_xor_sync(0xffffffffu, s, 1);
        s += __shfl_xor_sync(0xffffffffu, s, 2);
        s += __shfl_xor_sync(0xffffffffu, s, 4);
        if (sub == 0 && pos < 100) sh_dot[side][pos] = s;
    }
    __syncthreads();

    // --- bilinear combine: t<162 -> (k = t/2, sd = t&1); pairwise 8B stores
    if (t < 162) {
        int k  = t >> 1;
        int sd = t & 1;
        float cx2 = sh_c[sd][0], cy2 = sh_c[sd][1];
        int ix2 = (int)floorf(cx2);
        int iy2 = (int)floorf(cy2);
        int dxi = k / 9, dyi = k - dxi * 9;
        float xq = fminf(fmaxf(cx2 + (float)(dxi - 4), 0.f), (float)(Wl - 1));
        float yq = fminf(fmaxf(cy2 + (float)(dyi - 4), 0.f), (float)(Hl - 1));
        float x0f = floorf(xq), y0f = floorf(yq);
        float wx1 = xq - x0f,  wy1 = yq - y0f;
        float wx0 = 1.f - wx1, wy0 = 1.f - wy1;
        int t0x = min(max((int)x0f - ix2 + 4, 0), 9), t1x = min(t0x + 1, 9);
        int t0y = min(max((int)y0f - iy2 + 4, 0), 9), t1y = min(t0y + 1, 9);
        float v = wy0 * (wx0 * sh_dot[sd][t0y * 10 + t0x] + wx1 * sh_dot[sd][t0y * 10 + t1x])
                + wy1 * (wx0 * sh_dot[sd][t1y * 10 + t0x] + wx1 * sh_dot[sd][t1y * 10 + t1x]);
        out[ooff + k * (Hl * Wl) + 2 * q + sd] = v * 0.08838834764831845f;  // 1/sqrt(128)
    }
}

// ---------------------------------------------------------------------------
extern "C" void kernel_launch(void* const* d_in, const int* in_sizes, int n_in,
                              void* d_out, int out_size) {
    const float* f1     = (const float*)d_in[0];
    const float* f2     = (const float*)d_in[1];
    const float* coords = (const float*)d_in[2];
    float* out = (float*)d_out;

    build_kernel<<<dim3(96, 1, 2), 512>>>(f1, f2);
    corr_kernel<<<4144, 256>>>(coords, out);
}